// round 6
// baseline (speedup 1.0000x reference)
#include <cuda_runtime.h>
#include <stdint.h>

#define NN    20000
#define EE    200000
#define PP    300
#define EPE   2000
#define KKEEP 16000
#define HS    4096
#define HM    4095
#define NB2   2048      // bins per histogram copy
#define NT    1024
#define NITER 20        // ceil(NN/NT)

// dynamic smem layout (bytes):
//   ukey : 20000 u32        [0,      80000)
//   keysh: 4096  u16        [80000,  88192)
//   hist : 2*2048 u32       [88192, 104576)   (also dl[4000] / scratch)
//   wbuf : 32 f32           [104576,104704)
#define SMEM_BYTES 104704

__device__ float4 g_h4[NN];
__device__ float  g_hp[NN * 3];
__device__ float  g_agg[NN * 3];
__device__ float4 g_mv[PP * HS];   // zero-initialized; every run restores zeros
__device__ float  g_pathC[PP];

__device__ __forceinline__ unsigned fkey(float f) {
    unsigned u = __float_as_uint(f);
    return (u & 0x80000000u) ? ~u : (u | 0x80000000u);
}

__device__ __forceinline__ float tanh_fast(float x) {
    float a = fabsf(x);
    if (a < 0.53f) {
        float x2 = x * x;
        float p = fmaf(x2, -5.3968254e-2f, 1.3333333e-1f);
        p = fmaf(x2, p, -3.3333333e-1f);
        p = fmaf(x2, p, 1.0f);
        return x * p;
    }
    return tanhf(x);
}
__device__ __forceinline__ float exp_fast(float t) {
    if (fabsf(t) < 0.3f) {
        float p = fmaf(t, 4.1666668e-2f, 1.6666667e-1f);
        p = fmaf(t, p, 0.5f);
        p = fmaf(t, p, 1.0f);
        p = fmaf(t, p, 1.0f);
        return p;
    }
    return __expf(t);
}

// W layout in smem: [0..8]=Wl, [9..17]=Wr, [18..20]=bl, [21..23]=wrel,
//                   [24..26]=wroot, [27]=pb, [28..30]=gW
__device__ __forceinline__ void node_val_m(
    float4 hv, float m0, float m1, float m2, float ar, const float* W,
    unsigned& u, float& e, float& k0, float& k1, float& k2)
{
    float t0 = fmaf(hv.x, W[9],  fmaf(hv.y, W[12], fmaf(hv.z, W[15], W[18])));
    float t1 = fmaf(hv.x, W[10], fmaf(hv.y, W[13], fmaf(hv.z, W[16], W[19])));
    float t2 = fmaf(hv.x, W[11], fmaf(hv.y, W[14], fmaf(hv.z, W[17], W[20])));
    float xc0 = fmaxf(fmaf(m0, W[0], fmaf(m1, W[3], fmaf(m2, W[6], t0))), 0.f);
    float xc1 = fmaxf(fmaf(m0, W[1], fmaf(m1, W[4], fmaf(m2, W[7], t1))), 0.f);
    float xc2 = fmaxf(fmaf(m0, W[2], fmaf(m1, W[5], fmaf(m2, W[8], t2))), 0.f);
    float sc = fmaf(xc0, W[24], fmaf(xc1, W[25], fmaf(xc2, W[26], W[27] + ar)));
    u = fkey(sc);
    float tv = tanh_fast(sc);
    k0 = xc0 * tv; k1 = xc1 * tv; k2 = xc2 * tv;
    float l = fmaf(k0, W[28], fmaf(k1, W[29], k2 * W[30]));
    e = exp_fast(l);
}

__device__ __forceinline__ int hfind(int key, const unsigned short* ks) {
    unsigned slot = ((unsigned)key * 2654435761u) >> 20;
    unsigned short want = (unsigned short)(key + 1);
    for (;;) {
        unsigned short k2 = ks[slot];
        if (k2 == want) return (int)slot;
        if (k2 == 0) return -1;
        slot = (slot + 1) & HM;
    }
}

// ---------------- global stage ----------------
__global__ void k_hp(const float* __restrict__ x, const float* __restrict__ Wp,
                     const float* __restrict__ bp) {
    int i = blockIdx.x * blockDim.x + threadIdx.x;
    if (i >= NN) return;
    float x0 = x[3*i], x1 = x[3*i+1], x2 = x[3*i+2];
#pragma unroll
    for (int c = 0; c < 3; c++) {
        float v = fmaxf(bp[c] + x0*Wp[c] + x1*Wp[3+c] + x2*Wp[6+c], 0.f);
        g_hp[3*i+c] = v;
        g_agg[3*i+c] = v;
    }
}

__global__ void k_segmax(const int* __restrict__ ei) {
    int e = blockIdx.x * blockDim.x + threadIdx.x;
    if (e >= EE) return;
    int s = ei[e], d = ei[EE + e];
#pragma unroll
    for (int c = 0; c < 3; c++)
        atomicMax((int*)&g_agg[3*d+c], __float_as_int(g_hp[3*s+c]));
}

__global__ void k_h(const float* __restrict__ x, const float* __restrict__ Ws,
                    const float* __restrict__ Wn, const float* __restrict__ bc) {
    int i = blockIdx.x * blockDim.x + threadIdx.x;
    if (i >= NN) return;
    float x0 = x[3*i], x1 = x[3*i+1], x2 = x[3*i+2];
    float a0 = g_agg[3*i], a1 = g_agg[3*i+1], a2 = g_agg[3*i+2];
    float4 o;
    o.x = tanhf(bc[0] + x0*Ws[0] + x1*Ws[3] + x2*Ws[6] + a0*Wn[0] + a1*Wn[3] + a2*Wn[6]);
    o.y = tanhf(bc[1] + x0*Ws[1] + x1*Ws[4] + x2*Ws[7] + a0*Wn[1] + a1*Wn[4] + a2*Wn[7]);
    o.z = tanhf(bc[2] + x0*Ws[2] + x1*Ws[5] + x2*Ws[8] + a0*Wn[2] + a1*Wn[5] + a2*Wn[8]);
    o.w = 0.f;
    g_h4[i] = o;
}

// ---------------- fused per-pathway kernel, 2 CTAs/SM ----------------
__global__ void __launch_bounds__(NT, 2) k_path(
    const int*   __restrict__ pe,
    const float* __restrict__ subWl, const float* __restrict__ subbl,
    const float* __restrict__ subWr,
    const float* __restrict__ pWrel, const float* __restrict__ pWroot,
    const float* __restrict__ poolb,
    const float* __restrict__ gateW, const float* __restrict__ gateb,
    const float* __restrict__ linW,  const float* __restrict__ linb,
    const float* __restrict__ mlpW)
{
    extern __shared__ char sm[];
    unsigned*       ukey  = (unsigned*)(sm);
    unsigned short* keysh = (unsigned short*)(sm + 80000);
    unsigned*       hist  = (unsigned*)(sm + 88192);
    float*          wb    = (float*)(sm + 104576);

    __shared__ unsigned s_wa[32], s_wb[32];
    __shared__ unsigned s_bin, s_rem, s_cnt, s_itie, s_dn;
    __shared__ float    fred[128];

    const int p    = blockIdx.x;
    const int tid  = threadIdx.x;
    const int lane = tid & 31;
    const int wid  = tid >> 5;

    // ---- phase 0: init keysh + load weights to smem ----
    ((unsigned*)keysh)[tid]        = 0;
    ((unsigned*)keysh)[tid + NT]   = 0;
    if (tid < 9)        wb[tid] = __ldg(subWl  + 9*p + tid);
    else if (tid < 18)  wb[tid] = __ldg(subWr  + 9*p + tid - 9);
    else if (tid < 21)  wb[tid] = __ldg(subbl  + 3*p + tid - 18);
    else if (tid < 24)  wb[tid] = __ldg(pWrel  + 3*p + tid - 21);
    else if (tid < 27)  wb[tid] = __ldg(pWroot + 3*p + tid - 24);
    else if (tid == 27) wb[tid] = __ldg(poolb + p);
    else if (tid < 31)  wb[tid] = __ldg(gateW + 3*p + tid - 28);
    __syncthreads();
    const float* W = wb;

    const int* ps = pe + p * 2 * EPE;
    const int* pd = ps + EPE;
    float* gm = (float*)(g_mv + p * HS);

    // ---- phase 1a: CAS-insert dst keys (u16 smem hash) ----
    int slotA = -1, slotB = -1;
    {
        int d = pd[tid];
        unsigned slot = ((unsigned)d * 2654435761u) >> 20;
        unsigned short want = (unsigned short)(d + 1);
        for (;;) {
            unsigned short prev = atomicCAS(&keysh[slot], (unsigned short)0, want);
            if (prev == 0 || prev == want) break;
            slot = (slot + 1) & HM;
        }
        slotA = (int)slot;
    }
    if (tid + NT < EPE) {
        int d = pd[tid + NT];
        unsigned slot = ((unsigned)d * 2654435761u) >> 20;
        unsigned short want = (unsigned short)(d + 1);
        for (;;) {
            unsigned short prev = atomicCAS(&keysh[slot], (unsigned short)0, want);
            if (prev == 0 || prev == want) break;
            slot = (slot + 1) & HM;
        }
        slotB = (int)slot;
    }

    // ---- phase 1b: accumulate msum/cnt into g_mv (global atomics) ----
    {
        float4 hv = __ldg(&g_h4[ps[tid]]);
        atomicAdd(&gm[4*slotA],   hv.x);
        atomicAdd(&gm[4*slotA+1], hv.y);
        atomicAdd(&gm[4*slotA+2], hv.z);
        atomicAdd(&gm[4*slotA+3], 1.f);
    }
    if (slotB >= 0) {
        float4 hv = __ldg(&g_h4[ps[tid + NT]]);
        atomicAdd(&gm[4*slotB],   hv.x);
        atomicAdd(&gm[4*slotB+1], hv.y);
        atomicAdd(&gm[4*slotB+2], hv.z);
        atomicAdd(&gm[4*slotB+3], 1.f);
    }
    __syncthreads();

    // ---- phase 1c: normalize mean, zero arel ----
    for (int slot = tid; slot < HS; slot += NT) {
        if (keysh[slot] != 0) {
            float4 v = __ldcg(&g_mv[p*HS + slot]);
            float inv = 1.f / v.w;
            g_mv[p*HS + slot] = make_float4(v.x * inv, v.y * inv, v.z * inv, 0.f);
        }
    }
    __syncthreads();

    // ---- phase 2: arel[d] += xc(s) . Wrel ----
#pragma unroll
    for (int ee = 0; ee < 2; ee++) {
        int e = tid + ee * NT;
        int myslot = (ee == 0) ? slotA : slotB;
        if (e < EPE) {
            int s = ps[e];
            float4 hv = __ldg(&g_h4[s]);
            float m0 = 0.f, m1 = 0.f, m2 = 0.f;
            int sl = hfind(s, keysh);
            if (sl >= 0) {
                float4 mm = g_mv[p*HS + sl];   // xyz written by 1c stores (fresh), w unused
                m0 = mm.x; m1 = mm.y; m2 = mm.z;
            }
            float t0 = fmaf(hv.x, W[9],  fmaf(hv.y, W[12], fmaf(hv.z, W[15], W[18])));
            float t1 = fmaf(hv.x, W[10], fmaf(hv.y, W[13], fmaf(hv.z, W[16], W[19])));
            float t2 = fmaf(hv.x, W[11], fmaf(hv.y, W[14], fmaf(hv.z, W[17], W[20])));
            float xc0 = fmaxf(fmaf(m0, W[0], fmaf(m1, W[3], fmaf(m2, W[6], t0))), 0.f);
            float xc1 = fmaxf(fmaf(m0, W[1], fmaf(m1, W[4], fmaf(m2, W[7], t1))), 0.f);
            float xc2 = fmaxf(fmaf(m0, W[2], fmaf(m1, W[5], fmaf(m2, W[8], t2))), 0.f);
            float vv = fmaf(xc0, W[21], fmaf(xc1, W[22], xc2 * W[23]));
            atomicAdd(&gm[4*myslot+3], vv);
        }
    }
    __syncthreads();

    // ---- phase 3: score all nodes (non-member form), accumulate all-sums ----
    float ssum = 0.f, a0 = 0.f, a1 = 0.f, a2 = 0.f;
    unsigned mymin = 0xffffffffu, mymax = 0u;
    for (int i = tid; i < NN; i += NT) {
        float4 hv = __ldg(&g_h4[i]);
        unsigned u; float e, k0, k1, k2;
        node_val_m(hv, 0.f, 0.f, 0.f, 0.f, W, u, e, k0, k1, k2);
        ukey[i] = u;
        mymin = min(mymin, u); mymax = max(mymax, u);
        ssum += e;
        a0 = fmaf(e, k0, a0); a1 = fmaf(e, k1, a1); a2 = fmaf(e, k2, a2);
    }
    __syncthreads();

    // ---- phase 4: member fixup; cache contribution (e, e*k) in g_mv ----
    for (int slot = tid; slot < HS; slot += NT) {
        unsigned short kk = keysh[slot];
        if (kk != 0) {
            int d = (int)kk - 1;
            float4 mm = __ldcg(&g_mv[p*HS + slot]);   // xyz mean (L2 fresh) + w arel (atomics)
            float4 hv = __ldg(&g_h4[d]);
            unsigned uo; float eo, o0, o1, o2;
            node_val_m(hv, 0.f, 0.f, 0.f, 0.f, W, uo, eo, o0, o1, o2);
            unsigned un; float en, n0, n1, n2;
            node_val_m(hv, mm.x, mm.y, mm.z, mm.w, W, un, en, n0, n1, n2);
            ukey[d] = un;
            mymin = min(mymin, un); mymax = max(mymax, un);
            ssum += en - eo;
            float c1 = en*n0, c2 = en*n1, c3 = en*n2;
            a0 += c1 - eo*o0; a1 += c2 - eo*o1; a2 += c3 - eo*o2;
            g_mv[p*HS + slot] = make_float4(en, c1, c2, c3);   // cached contribution
        }
    }

    // ---- block min/max ----
    mymin = __reduce_min_sync(0xffffffffu, mymin);
    mymax = __reduce_max_sync(0xffffffffu, mymax);
    if (lane == 0) { s_wa[wid] = mymin; s_wb[wid] = mymax; }
    __syncthreads();
    if (wid == 0) {
        unsigned mn = __reduce_min_sync(0xffffffffu, s_wa[lane]);
        unsigned mx = __reduce_max_sync(0xffffffffu, s_wb[lane]);
        if (lane == 0) { s_wa[0] = mn; s_wb[0] = mx; }
    }
    __syncthreads();
    unsigned lo = s_wa[0], hi = s_wb[0];
    __syncthreads();

    // ---- phase 5: adaptive radix select, 2-copy 2048-bin hist ----
    unsigned rem = KKEEP, ceq = NN;
    while (lo < hi) {
        unsigned width = hi - lo;
        int bits = 32 - __clz(width);
        int shift = bits > 11 ? bits - 11 : 0;
        ((uint4*)hist)[tid] = make_uint4(0, 0, 0, 0);
        __syncthreads();
        unsigned* myh = hist + ((wid & 1) ? NB2 : 0);
        for (int it = 0; it < NITER; it++) {
            int i = it * NT + tid;
            unsigned bin = 0xffffffffu;
            if (i < NN) {
                unsigned u = ukey[i];
                if (u >= lo && u <= hi) bin = (u - lo) >> shift;
            }
            unsigned msk = __match_any_sync(0xffffffffu, bin);
            if (bin != 0xffffffffu && (__ffs(msk) - 1) == lane)
                atomicAdd(&myh[bin], __popc(msk));
        }
        __syncthreads();
        uint2 h0 = ((uint2*)hist)[tid];
        uint2 h1 = ((uint2*)(hist + NB2))[tid];
        unsigned bt0 = h0.x + h1.x, bt1 = h0.y + h1.y;
        unsigned psum = bt0 + bt1;
        unsigned v = psum;
#pragma unroll
        for (int d = 1; d < 32; d <<= 1) { unsigned t = __shfl_down_sync(~0u, v, d); if (lane + d < 32) v += t; }
        if (lane == 0) s_wa[wid] = v;
        __syncthreads();
        if (wid == 0) {
            unsigned x = s_wa[lane];
#pragma unroll
            for (int d = 1; d < 32; d <<= 1) { unsigned t = __shfl_down_sync(~0u, x, d); if (lane + d < 32) x += t; }
            s_wb[lane] = x;
        }
        __syncthreads();
        unsigned c = ((wid < 31) ? s_wb[wid + 1] : 0u) + (v - psum);
        if (c < rem && c + bt1 >= rem) { s_bin = tid*2 + 1; s_cnt = bt1; s_rem = rem - c; }
        c += bt1;
        if (c < rem && c + bt0 >= rem) { s_bin = tid*2;     s_cnt = bt0; s_rem = rem - c; }
        __syncthreads();
        unsigned bin = s_bin; rem = s_rem; ceq = s_cnt;
        unsigned nlo = lo + (bin << shift);
        unsigned long long nh = (unsigned long long)nlo + ((shift > 0) ? ((1ull << shift) - 1ull) : 0ull);
        hi = (nh > (unsigned long long)hi) ? hi : (unsigned)nh;
        lo = nlo;
        __syncthreads();
    }
    const unsigned Tu = lo;
    unsigned Itie = NN;

    // ---- phase 6: single-pass index tie-break ----
    if (rem < ceq) {
        ((uint4*)hist)[tid] = make_uint4(0, 0, 0, 0);
        __syncthreads();
        unsigned* myh = hist + ((wid & 1) ? NB2 : 0);
        for (int it = 0; it < NITER; it++) {
            int i = it * NT + tid;
            unsigned bin = 0xffffffffu;
            if (i < NN && ukey[i] == Tu) bin = (unsigned)i >> 5;
            unsigned msk = __match_any_sync(0xffffffffu, bin);
            if (bin != 0xffffffffu && (__ffs(msk) - 1) == lane)
                atomicAdd(&myh[bin], __popc(msk));
        }
        __syncthreads();
        unsigned psum = (tid < 625) ? (hist[tid] + hist[NB2 + tid]) : 0u;
        unsigned v = psum;
#pragma unroll
        for (int d = 1; d < 32; d <<= 1) { unsigned t = __shfl_up_sync(~0u, v, d); if (lane >= d) v += t; }
        if (lane == 31) s_wa[wid] = v;
        __syncthreads();
        if (wid == 0) {
            unsigned x = s_wa[lane];
#pragma unroll
            for (int d = 1; d < 32; d <<= 1) { unsigned t = __shfl_up_sync(~0u, x, d); if (lane >= d) x += t; }
            s_wb[lane] = x;
        }
        __syncthreads();
        unsigned below = (v - psum) + ((wid > 0) ? s_wb[wid - 1] : 0u);
        if (tid < 625 && below < rem && below + psum >= rem) { s_bin = tid; s_rem = rem - below; }
        __syncthreads();
        int bA = (int)s_bin; unsigned r2 = s_rem;
        if (wid == 0) {
            int i = bA * 32 + lane;
            bool f = (i < NN) && (ukey[i] == Tu);
            unsigned m = __ballot_sync(0xffffffffu, f);
            unsigned rk = __popc(m & ((1u << lane) - 1u)) + 1u;
            if (f && rk == r2) s_itie = (unsigned)i;
        }
        __syncthreads();
        Itie = s_itie;
    }

    // ---- phase 7: compact dropped nodes into hist region (<=4000 <= 4096) ----
    if (tid == 0) s_dn = 0;
    __syncthreads();
    int* dl = (int*)hist;
    for (int it = 0; it < NITER; it++) {
        int i = it * NT + tid;
        bool dr = false;
        if (i < NN) {
            unsigned u = ukey[i];
            dr = !((u > Tu) || (u == Tu && (unsigned)i <= Itie));
        }
        unsigned m = __ballot_sync(0xffffffffu, dr);
        if (m) {
            int leader = __ffs(m) - 1;
            unsigned base = 0;
            if (lane == leader) base = atomicAdd(&s_dn, __popc(m));
            base = __shfl_sync(0xffffffffu, base, leader);
            if (dr) dl[base + __popc(m & ((1u << lane) - 1u))] = i;
        }
    }
    __syncthreads();

    // ---- phase 8: subtract dropped contributions ----
    {
        int D = (int)s_dn;
        for (int k = tid; k < D; k += NT) {
            int i = dl[k];
            int sl = hfind(i, keysh);
            if (sl >= 0) {
                float4 c = g_mv[p*HS + sl];     // contribution cached by phase 4
                ssum -= c.x; a0 -= c.y; a1 -= c.z; a2 -= c.w;
            } else {
                float4 hv = __ldg(&g_h4[i]);
                unsigned uu; float e, k0, k1, k2v;
                node_val_m(hv, 0.f, 0.f, 0.f, 0.f, W, uu, e, k0, k1, k2v);
                ssum -= e;
                a0 -= e * k0; a1 -= e * k1; a2 -= e * k2v;
            }
        }
    }
    __syncthreads();

    // ---- phase 8b: restore g_mv zeros (graph-replay invariant) ----
    for (int slot = tid; slot < HS; slot += NT) {
        if (keysh[slot] != 0)
            g_mv[p*HS + slot] = make_float4(0.f, 0.f, 0.f, 0.f);
    }

    // ---- phase 9: final reduction + output ----
#pragma unroll
    for (int off = 16; off > 0; off >>= 1) {
        ssum += __shfl_down_sync(0xffffffffu, ssum, off);
        a0   += __shfl_down_sync(0xffffffffu, a0, off);
        a1   += __shfl_down_sync(0xffffffffu, a1, off);
        a2   += __shfl_down_sync(0xffffffffu, a2, off);
    }
    if (lane == 0) { fred[wid] = ssum; fred[32+wid] = a0; fred[64+wid] = a1; fred[96+wid] = a2; }
    __syncthreads();
    if (tid == 0) {
        float S = 0.f, A0 = 0.f, A1 = 0.f, A2 = 0.f;
#pragma unroll
        for (int q = 0; q < 32; q++) { S += fred[q]; A0 += fred[32+q]; A1 += fred[64+q]; A2 += fred[96+q]; }
        float inv = 1.f / S;
        float v0 = fmaxf(A0 * inv, 0.f);
        float v1 = fmaxf(A1 * inv, 0.f);
        float v2 = fmaxf(A2 * inv, 0.f);
        float rr = fmaxf(v0 * __ldg(linW) + v1 * __ldg(linW+1) + v2 * __ldg(linW+2) + __ldg(linb), 0.f);
        g_pathC[p] = rr * __ldg(mlpW + p);
    }
}

__global__ void k_out(const float* __restrict__ mlpb, float* __restrict__ out) {
    __shared__ float sbuf[256];
    int tid = threadIdx.x;
    float v = 0.f;
    for (int i = tid; i < PP; i += 256) v += g_pathC[i];
    sbuf[tid] = v;
    __syncthreads();
    for (int s = 128; s > 0; s >>= 1) { if (tid < s) sbuf[tid] += sbuf[tid + s]; __syncthreads(); }
    if (tid == 0) out[0] = 1.f / (1.f + expf(-(sbuf[0] + mlpb[0])));
}

// ---------------- launch ----------------
extern "C" void kernel_launch(void* const* d_in, const int* in_sizes, int n_in,
                              void* d_out, int out_size) {
    const float* x          = (const float*)d_in[0];
    const int*   edge_index = (const int*)  d_in[1];
    const int*   path_edges = (const int*)  d_in[2];
    const float* W_pool     = (const float*)d_in[3];
    const float* b_pool     = (const float*)d_in[4];
    const float* W_self     = (const float*)d_in[5];
    const float* W_neigh    = (const float*)d_in[6];
    const float* b_conv     = (const float*)d_in[7];
    const float* sub_Wl     = (const float*)d_in[8];
    const float* sub_bl     = (const float*)d_in[9];
    const float* sub_Wr     = (const float*)d_in[10];
    const float* pool_Wrel  = (const float*)d_in[11];
    const float* pool_Wroot = (const float*)d_in[12];
    const float* pool_b     = (const float*)d_in[13];
    const float* gate_W     = (const float*)d_in[14];
    const float* gate_b     = (const float*)d_in[15];
    const float* lin_W      = (const float*)d_in[16];
    const float* lin_b      = (const float*)d_in[17];
    const float* mlp_W      = (const float*)d_in[18];
    const float* mlp_b      = (const float*)d_in[19];
    float* out = (float*)d_out;
    (void)gate_b;   // constant gate bias cancels in softmax

    cudaFuncSetAttribute(k_path, cudaFuncAttributeMaxDynamicSharedMemorySize, SMEM_BYTES);

    k_hp     <<<(NN + 255) / 256, 256>>>(x, W_pool, b_pool);
    k_segmax <<<(EE + 511) / 512, 512>>>(edge_index);
    k_h      <<<(NN + 255) / 256, 256>>>(x, W_self, W_neigh, b_conv);
    k_path   <<<PP, NT, SMEM_BYTES>>>(path_edges, sub_Wl, sub_bl, sub_Wr,
                                      pool_Wrel, pool_Wroot, pool_b,
                                      gate_W, gate_b, lin_W, lin_b, mlp_W);
    k_out    <<<1, 256>>>(mlp_b, out);
}